// round 6
// baseline (speedup 1.0000x reference)
#include <cuda_runtime.h>
#include <cuda_fp16.h>
#include <cstdint>

// Problem constants
#define Bn  16
#define Cc  256
#define HWc 4096
#define Nq  65536
#define Kc  1024
#define ZQ_ELEMS 16777216

#define FLAG_THRESH 5e-4f
#define FINF __int_as_float(0x7f800000)

// -------------------------- device scratch --------------------------------
__device__ float  g_cbT[Cc * Kc];       // codebook transposed [C][K] (write_zq)
__device__ float  g_bnorm[Kc];          // ||c_k||^2 (same chain as R1)
__device__ __half2 g_cbp[(Cc / 2) * Kc]; // codebook c-pairs [cp][k] fp16
__device__ int    g_idx[Nq];
__device__ float  g_dbest[Nq];
__device__ int    g_fix_count;
__device__ int    g_fix_list[Nq];

// -------------------------- smem layout (bytes) ----------------------------
#define OFF_AS   0            // float As[64]
#define OFF_BN   256          // float bn[1024]
#define OFF_ZH   4352         // half2 zh[128*64]  (32KB)
#define OFF_Z32  37120        // float zt32[256*64] (64KB), aliased by cs (8KB)
#define SMEM_BYTES 102656

// ---------------------------------------------------------------------------
// Prep: cbT + bnorm (identical chain to R1) + fp16 c-pair codebook + reset
// ---------------------------------------------------------------------------
__global__ void prep_kernel(const float* __restrict__ cb) {
    int k = blockIdx.x, c = threadIdx.x;
    float v = cb[k * Cc + c];
    g_cbT[c * Kc + k] = v;
    __shared__ float sval[256];
    __shared__ float sred[256];
    sval[c] = v;
    sred[c] = v * v;
    __syncthreads();
    if (c < 128)
        g_cbp[c * Kc + k] = __floats2half2_rn(sval[2 * c], sval[2 * c + 1]);
    for (int s = 128; s > 0; s >>= 1) {
        if (c < s) sred[c] += sred[c + s];
        __syncthreads();
    }
    if (c == 0) {
        g_bnorm[k] = sred[0];
        if (k == 0) g_fix_count = 0;
    }
}

// ---------------------------------------------------------------------------
// Main HFMA2 kernel: 1024 CTAs x 128 threads. Per CTA: 64 queries vs all
// 1024 codes. Each (q,k) dot accumulated as one packed fp16 even/odd chain
// (128 hfma2), folded to fp32 once in the epilogue.
// Thread (tx, ty): queries 8*ty..8*ty+7; codes {2tx+32j, 2tx+32j+1} j=0..3.
// ---------------------------------------------------------------------------
__global__ void __launch_bounds__(128, 2) vq_half(const float* __restrict__ z) {
    extern __shared__ char smem[];
    float*   As   = (float*)(smem + OFF_AS);
    float*   bn   = (float*)(smem + OFF_BN);
    __half2* zh   = (__half2*)(smem + OFF_ZH);
    float*   zt32 = (float*)(smem + OFF_Z32);
    __half2* cs   = (__half2*)(smem + OFF_Z32);   // alias (zt32 dead after conv)

    const int tid = threadIdx.x;
    const int tx = tid & 15, ty = tid >> 4;
    const int n0 = blockIdx.x * 64;
    const float* zb = z + (size_t)(n0 >> 12) * (Cc * HWc) + (n0 & (HWc - 1));

    // ---- stage z fp32 [256 c][64 q] (coalesced) + bnorm to smem ----
    const float4* zb4 = (const float4*)zb;
    #pragma unroll
    for (int i = 0; i < 32; ++i) {
        int c = (tid >> 4) + 8 * i;
        ((float4*)zt32)[c * 16 + tx] = zb4[(size_t)c * 1024 + tx];
    }
    #pragma unroll
    for (int i = 0; i < 8; ++i) bn[tid + 128 * i] = g_bnorm[tid + 128 * i];
    __syncthreads();

    // ---- norms: exact R1 sequential fmaf chain over c ascending ----
    if (tid < 64) {
        float a = 0.f;
        #pragma unroll 8
        for (int c = 0; c < Cc; ++c) {
            float v = zt32[c * 64 + tid];
            a = fmaf(v, v, a);
        }
        As[tid] = a;
    }
    // ---- convert z to fp16 c-pairs: zh[cp][q] ----
    #pragma unroll
    for (int i = 0; i < 64; ++i) {
        int idx = tid + 128 * i;            // 0..8191
        int cp = idx >> 6, q = idx & 63;
        zh[cp * 64 + q] = __floats2half2_rn(zt32[(2 * cp) * 64 + q],
                                            zt32[(2 * cp + 1) * 64 + q]);
    }
    __syncthreads();                         // zt32 dead; cs region usable

    float Aq[8];
    #pragma unroll
    for (int qi = 0; qi < 8; ++qi) Aq[qi] = As[8 * ty + qi];

    float lm1[8], lm2[8]; int li[8];
    #pragma unroll
    for (int qi = 0; qi < 8; ++qi) { lm1[qi] = FINF; lm2[qi] = FINF; li[qi] = 0; }

    const uint4* cbp4 = (const uint4*)g_cbp;     // row = 256 uint4 per cp
    uint4* cs4 = (uint4*)cs;
    const uint4* zh4 = (const uint4*)zh;         // row = 16 uint4 per cp

    for (int kt = 0; kt < 8; ++kt) {
        __half2 acc[8][8];
        const __half2 h2z = __floats2half2_rn(0.f, 0.f);
        #pragma unroll
        for (int qi = 0; qi < 8; ++qi)
            #pragma unroll
            for (int kj = 0; kj < 8; ++kj) acc[qi][kj] = h2z;

        for (int cc = 0; cc < 4; ++cc) {
            // stage cs[32 cp][128 k] fp16 pairs (8KB), coalesced
            #pragma unroll
            for (int i = 0; i < 8; ++i) {
                int lin = tid + 128 * i;             // 0..1023
                int cpl = lin >> 5, k16 = lin & 31;
                cs4[cpl * 32 + k16] =
                    cbp4[(size_t)(cc * 32 + cpl) * 256 + kt * 32 + k16];
            }
            __syncthreads();

            #pragma unroll 4
            for (int cp = 0; cp < 32; ++cp) {
                // a: 8 queries' c-pairs = 2 x LDS.128 (broadcast across tx)
                int za = (cc * 32 + cp) * 16 + 2 * ty;
                uint4 a0 = zh4[za];
                uint4 a1 = zh4[za + 1];
                __half2 ah[8];
                ah[0] = *(__half2*)&a0.x; ah[1] = *(__half2*)&a0.y;
                ah[2] = *(__half2*)&a0.z; ah[3] = *(__half2*)&a0.w;
                ah[4] = *(__half2*)&a1.x; ah[5] = *(__half2*)&a1.y;
                ah[6] = *(__half2*)&a1.z; ah[7] = *(__half2*)&a1.w;
                // b: 8 codes' c-pairs = 4 x LDS.64, lane-contiguous (no conflicts)
                const uint2* csu2 = (const uint2*)(cs + cp * 128);
                __half2 bh[8];
                #pragma unroll
                for (int j = 0; j < 4; ++j) {
                    uint2 bb = csu2[tx + 16 * j];
                    bh[2 * j]     = *(__half2*)&bb.x;
                    bh[2 * j + 1] = *(__half2*)&bb.y;
                }
                #pragma unroll
                for (int qi = 0; qi < 8; ++qi)
                    #pragma unroll
                    for (int kj = 0; kj < 8; ++kj)
                        acc[qi][kj] = __hfma2(ah[qi], bh[kj], acc[qi][kj]);
            }
            __syncthreads();     // before next chunk overwrites cs
        }

        // epilogue: fold fp16 pair -> fp32 dot, distances, min1/min2
        #pragma unroll
        for (int qi = 0; qi < 8; ++qi)
            #pragma unroll
            for (int j = 0; j < 4; ++j)
                #pragma unroll
                for (int e = 0; e < 2; ++e) {
                    int kj = 2 * j + e;
                    float dot = __low2float(acc[qi][kj]) + __high2float(acc[qi][kj]);
                    int k = kt * 128 + 32 * j + 2 * tx + e;
                    float d = fmaf(-2.f, dot, __fadd_rn(Aq[qi], bn[k]));
                    if (d < lm1[qi]) { lm2[qi] = lm1[qi]; lm1[qi] = d; li[qi] = k; }
                    else if (d < lm2[qi]) { lm2[qi] = d; }
                }
    }

    // ---- reduce over the 16 tx lanes (all in-warp), lowest-k tie-break ----
    #pragma unroll
    for (int qi = 0; qi < 8; ++qi) {
        #pragma unroll
        for (int off = 1; off <= 8; off <<= 1) {
            float om1 = __shfl_xor_sync(0xffffffffu, lm1[qi], off);
            float om2 = __shfl_xor_sync(0xffffffffu, lm2[qi], off);
            int   oi  = __shfl_xor_sync(0xffffffffu, li[qi], off);
            float nm2 = fminf(fminf(lm2[qi], om2), fmaxf(lm1[qi], om1));
            if (om1 < lm1[qi] || (om1 == lm1[qi] && oi < li[qi])) {
                lm1[qi] = om1; li[qi] = oi;
            }
            lm2[qi] = nm2;
        }
        if (tx == 0) {
            int q = n0 + 8 * ty + qi;
            g_idx[q] = li[qi];
            g_dbest[q] = lm1[qi];
            if (lm2[qi] - lm1[qi] <= FLAG_THRESH) {
                int s = atomicAdd(&g_fix_count, 1);
                g_fix_list[s] = q;
            }
        }
    }
}

// ---------------------------------------------------------------------------
// Fixup: exact fp32 recompute (R1 chain, proven rel_err 0.0) for near-ties.
// ---------------------------------------------------------------------------
__global__ void fixup_kernel(const float* __restrict__ z, const float* __restrict__ cb) {
    __shared__ float zq[256];
    __shared__ float rm[256];
    __shared__ int   rk[256];
    int cnt = g_fix_count;
    for (int it = blockIdx.x; it < cnt; it += gridDim.x) {
        int q = g_fix_list[it];
        int b = q >> 12, hw = q & 4095;
        zq[threadIdx.x] = z[((size_t)(b * 256 + threadIdx.x)) * 4096 + hw];
        __syncthreads();
        float A = 0.f;
        #pragma unroll 8
        for (int c = 0; c < 256; ++c) A = fmaf(zq[c], zq[c], A);
        float bm = FINF; int bk = 0;
        for (int t = 0; t < 4; ++t) {
            int k = threadIdx.x + 256 * t;
            const float* cr = cb + (size_t)k * 256;
            float dot = 0.f;
            #pragma unroll 8
            for (int c = 0; c < 256; ++c) dot = fmaf(zq[c], cr[c], dot);
            float d = fmaf(-2.f, dot, __fadd_rn(A, g_bnorm[k]));
            if (d < bm) { bm = d; bk = k; }          // k ascending per thread
        }
        rm[threadIdx.x] = bm; rk[threadIdx.x] = bk;
        __syncthreads();
        for (int s = 128; s > 0; s >>= 1) {
            if (threadIdx.x < s) {
                float v = rm[threadIdx.x + s]; int kk = rk[threadIdx.x + s];
                if (v < rm[threadIdx.x] ||
                    (v == rm[threadIdx.x] && kk < rk[threadIdx.x])) {
                    rm[threadIdx.x] = v; rk[threadIdx.x] = kk;
                }
            }
            __syncthreads();
        }
        if (threadIdx.x == 0) { g_idx[q] = rk[0]; g_dbest[q] = rm[0]; }
        __syncthreads();
    }
}

// ---------------------------------------------------------------------------
__global__ void write_zq(float* __restrict__ out, const float* __restrict__ z) {
    int p = blockIdx.x;               // b*256 + c
    int b = p >> 8, c = p & 255;
    const float* row  = g_cbT + (size_t)c * Kc;
    const int*   idxp = g_idx + b * HWc;
    const float* zp   = z + (size_t)p * HWc;
    float*       o    = out + (size_t)p * HWc;
    for (int hw = threadIdx.x; hw < HWc; hw += blockDim.x) {
        float zc = zp[hw];
        float zqv = row[idxp[hw]];
        o[hw] = __fadd_rn(zc, __fsub_rn(zqv, zc));
    }
}

__global__ void write_idx(float* __restrict__ out) {
    int n = blockIdx.x * blockDim.x + threadIdx.x;
    if (n < Nq) out[n] = (float)g_idx[n];
}

__global__ void loss_kernel(float* __restrict__ out) {
    __shared__ double sd[256];
    double s = 0.0;
    for (int i = threadIdx.x; i < Nq; i += 256) s += (double)g_dbest[i];
    sd[threadIdx.x] = s;
    __syncthreads();
    for (int r = 128; r > 0; r >>= 1) {
        if (threadIdx.x < r) sd[threadIdx.x] += sd[threadIdx.x + r];
        __syncthreads();
    }
    if (threadIdx.x == 0)
        out[0] = (float)(0.75 * sd[0] / (double)ZQ_ELEMS);
}

// ---------------------------------------------------------------------------
extern "C" void kernel_launch(void* const* d_in, const int* in_sizes, int n_in,
                              void* d_out, int out_size) {
    const float* z  = (const float*)d_in[0];   // [B,C,H,W] fp32
    const float* cb = (const float*)d_in[1];   // [K,C]     fp32
    float* out = (float*)d_out;

    cudaFuncSetAttribute(vq_half, cudaFuncAttributeMaxDynamicSharedMemorySize, SMEM_BYTES);

    prep_kernel<<<Kc, 256>>>(cb);
    vq_half<<<Nq / 64, 128, SMEM_BYTES>>>(z);
    fixup_kernel<<<4096, 256>>>(z, cb);
    write_zq<<<Bn * Cc, 256>>>(out, z);

    if (out_size >= ZQ_ELEMS + Nq)
        write_idx<<<Nq / 256, 256>>>(out + ZQ_ELEMS);
    if (out_size >= ZQ_ELEMS + Nq + 1)
        loss_kernel<<<1, 256>>>(out + ZQ_ELEMS + Nq);
    else if (out_size == ZQ_ELEMS + 1)
        loss_kernel<<<1, 256>>>(out + ZQ_ELEMS);
}

// round 8
// speedup vs baseline: 1.0081x; 1.0081x over previous
#include <cuda_runtime.h>
#include <cstdint>

// Problem constants
#define Bn  16
#define Cc  256
#define HWc 4096
#define Nq  65536
#define Kc  1024
#define ZQ_ELEMS 16777216

#define FLAG_THRESH 5e-4f
#define FINF __int_as_float(0x7f800000)
#define SCALE_C 130048.0f              // 127*1024
#define INV_SC  (1.0f/130048.0f)
#define INV_SC254 (1.0f/33032192.0f)   // 1/(130048*254)

// -------------------------- device scratch --------------------------------
__device__ float g_cbT[Cc * Kc];       // codebook transposed [C][K] (write_zq)
__device__ float g_bnorm[Kc];          // ||c_k||^2 (same chain as R1)
__device__ int   g_cbw[(Cc / 4) * Kc]; // codebook int8 packed words [w][k]
__device__ int   g_idx[Nq];
__device__ float g_dbest[Nq];
__device__ int   g_fix_count;
__device__ int   g_fix_list[Nq];

// -------------------------- smem layout (bytes) ----------------------------
#define OFF_ZT  0          // float  zt[256c][64q]   65536
#define OFF_ZH  65536      // int    zh[64w][64q]    16384  (hi bytes packed)
#define OFF_ZL  81920      // int    zl[64w][64q]    16384  (lo bytes packed)
#define OFF_CS  98304      // int    cs[16w][128k]    8192
#define OFF_BN  106496     // float  bn[1024]         4096
#define OFF_AS  110592     // float  As[64]
#define OFF_F1  110848     // float  qf1[64]
#define OFF_F2  111104     // float  qf2[64]
#define OFF_I1  111360     // float  qi1[64]
#define OFF_I2  111616     // float  qi2[64]
#define OFF_S1  111872     // float  qs1[64]
#define SMEM_BYTES 112128

// ---------------------------------------------------------------------------
// Prep: cbT + bnorm (identical chain to R1) + int8 packed codebook + reset
// ---------------------------------------------------------------------------
__global__ void prep_kernel(const float* __restrict__ cb) {
    int k = blockIdx.x, c = threadIdx.x;
    float v = cb[k * Cc + c];
    g_cbT[c * Kc + k] = v;
    __shared__ float sval[256];
    __shared__ float sred[256];
    sval[c] = v;
    sred[c] = v * v;
    __syncthreads();
    if (c < 64) {   // pack word w=c: channels 4c..4c+3, scale 127*1024
        int b0 = __float2int_rn(sval[4 * c]     * SCALE_C);
        int b1 = __float2int_rn(sval[4 * c + 1] * SCALE_C);
        int b2 = __float2int_rn(sval[4 * c + 2] * SCALE_C);
        int b3 = __float2int_rn(sval[4 * c + 3] * SCALE_C);
        g_cbw[c * Kc + k] = (b0 & 255) | ((b1 & 255) << 8) |
                            ((b2 & 255) << 16) | (b3 << 24);
    }
    for (int s = 128; s > 0; s >>= 1) {
        if (c < s) sred[c] += sred[c + s];
        __syncthreads();
    }
    if (c == 0) {
        g_bnorm[k] = sred[0];
        if (k == 0) g_fix_count = 0;
    }
}

// ---------------------------------------------------------------------------
// Main dp4a kernel: 1024 CTAs x 256 threads. Per CTA: 64 queries vs all 1024
// codes. z quantized per-query into two int8 levels (hi + residual); dot
// recombined in fp32: dot = f1*acc_hi + f2*acc_lo. Exact-fixup for near-ties.
// Thread (tx,ty): queries 4*ty..4*ty+3, codes 8*tx..8*tx+7 within each k-tile.
// ---------------------------------------------------------------------------
__global__ void __launch_bounds__(256, 2) vq_dp4a(const float* __restrict__ z) {
    extern __shared__ char smem[];
    float* zt  = (float*)(smem + OFF_ZT);
    int*   zh  = (int*)(smem + OFF_ZH);
    int*   zl  = (int*)(smem + OFF_ZL);
    int*   cs  = (int*)(smem + OFF_CS);
    float* bn  = (float*)(smem + OFF_BN);
    float* As  = (float*)(smem + OFF_AS);
    float* qf1 = (float*)(smem + OFF_F1);
    float* qf2 = (float*)(smem + OFF_F2);
    float* qi1 = (float*)(smem + OFF_I1);
    float* qi2 = (float*)(smem + OFF_I2);
    float* qs1 = (float*)(smem + OFF_S1);

    const int tid = threadIdx.x;
    const int tx = tid & 15, ty = tid >> 4;
    const int n0 = blockIdx.x * 64;
    const float* zb = z + (size_t)(n0 >> 12) * (Cc * HWc) + (n0 & (HWc - 1));

    // ---- stage z fp32 [256 c][64 q] (coalesced float4) + bnorm ----
    const float4* zb4 = (const float4*)zb;
    #pragma unroll
    for (int i = 0; i < 16; ++i) {
        int c = ty + 16 * i;
        ((float4*)zt)[c * 16 + tx] = zb4[(size_t)c * 1024 + tx];
    }
    #pragma unroll
    for (int i = 0; i < 4; ++i) bn[tid + 256 * i] = g_bnorm[tid + 256 * i];
    __syncthreads();

    // ---- norms (exact R1 fmaf chain) + per-query scales ----
    if (tid < 64) {
        float a = 0.f, mx = 0.f;
        #pragma unroll 8
        for (int c = 0; c < Cc; ++c) {
            float v = zt[c * 64 + tid];
            a = fmaf(v, v, a);
            mx = fmaxf(mx, fabsf(v));
        }
        As[tid] = a;
        float s  = fmaxf(mx, 1e-20f);
        float s1 = s * (1.0f / 127.0f);
        qs1[tid] = s1;
        qi1[tid] = 127.0f / s;
        qi2[tid] = 254.0f / s1;
        qf1[tid] = s1 * INV_SC;
        qf2[tid] = s1 * INV_SC254;
    }
    __syncthreads();

    // ---- quantize z -> two int8 levels, packed words zh/zl[w][q] ----
    {
        int q = tid & 63, wg = tid >> 6;           // 4 groups x 16 words
        float i1 = qi1[q], i2 = qi2[q], s1q = qs1[q];
        #pragma unroll 4
        for (int wi = 0; wi < 16; ++wi) {
            int w = wg * 16 + wi;
            int hp = 0, lp = 0;
            #pragma unroll
            for (int e = 0; e < 4; ++e) {
                float v  = zt[(4 * w + e) * 64 + q];
                float hf = rintf(v * i1);
                float r  = fmaf(-hf, s1q, v);
                int hi = (int)hf;
                int lo = __float2int_rn(r * i2);
                hp |= (hi & 255) << (8 * e);
                lp |= (lo & 255) << (8 * e);
            }
            zh[w * 64 + q] = hp;
            zl[w * 64 + q] = lp;
        }
    }
    __syncthreads();

    // ---- per-thread query constants ----
    float Av[4], f1v[4], f2v[4];
    #pragma unroll
    for (int i = 0; i < 4; ++i) {
        Av[i]  = As[4 * ty + i];
        f1v[i] = qf1[4 * ty + i];
        f2v[i] = qf2[4 * ty + i];
    }

    float lm1[4], lm2[4]; int li[4];
    #pragma unroll
    for (int i = 0; i < 4; ++i) { lm1[i] = FINF; lm2[i] = FINF; li[i] = 0; }

    const int4* zh4 = (const int4*)zh;   // row = 16 int4 per word
    const int4* zl4 = (const int4*)zl;
    const int4* cs4 = (const int4*)cs;   // row = 32 int4 per word

    for (int kt = 0; kt < 8; ++kt) {
        int acch[4][8], accl[4][8];
        #pragma unroll
        for (int i = 0; i < 4; ++i)
            #pragma unroll
            for (int j = 0; j < 8; ++j) { acch[i][j] = 0; accl[i][j] = 0; }

        for (int cc = 0; cc < 4; ++cc) {
            // stage cs[16 w][128 k] packed codebook words (coalesced int4)
            #pragma unroll
            for (int i = 0; i < 2; ++i) {
                int idx = tid + 256 * i;             // 0..511 int4
                int w = idx >> 5, col = idx & 31;
                ((int4*)cs)[idx] =
                    ((const int4*)(g_cbw + (size_t)(cc * 16 + w) * Kc + kt * 128))[col];
            }
            __syncthreads();

            #pragma unroll 4
            for (int w = 0; w < 16; ++w) {
                int4 ah = zh4[(cc * 16 + w) * 16 + ty];
                int4 al = zl4[(cc * 16 + w) * 16 + ty];
                int4 b0 = cs4[w * 32 + 2 * tx];
                int4 b1 = cs4[w * 32 + 2 * tx + 1];
                int av[4] = {ah.x, ah.y, ah.z, ah.w};
                int lv[4] = {al.x, al.y, al.z, al.w};
                int bv[8] = {b0.x, b0.y, b0.z, b0.w, b1.x, b1.y, b1.z, b1.w};
                #pragma unroll
                for (int i = 0; i < 4; ++i)
                    #pragma unroll
                    for (int j = 0; j < 8; ++j) {
                        acch[i][j] = __dp4a(av[i], bv[j], acch[i][j]);
                        accl[i][j] = __dp4a(lv[i], bv[j], accl[i][j]);
                    }
            }
            __syncthreads();     // before next chunk overwrites cs
        }

        // epilogue: recombine dot in fp32, distances, min1/min2 (k ascending)
        #pragma unroll
        for (int i = 0; i < 4; ++i)
            #pragma unroll
            for (int j = 0; j < 8; ++j) {
                float dot = fmaf((float)accl[i][j], f2v[i],
                                 (float)acch[i][j] * f1v[i]);
                int k = kt * 128 + 8 * tx + j;
                float d = fmaf(-2.f, dot, __fadd_rn(Av[i], bn[k]));
                if (d < lm1[i]) { lm2[i] = lm1[i]; lm1[i] = d; li[i] = k; }
                else if (d < lm2[i]) { lm2[i] = d; }
            }
    }

    // ---- reduce across the 16 tx lanes (in-warp), lowest-k tie-break ----
    #pragma unroll
    for (int i = 0; i < 4; ++i) {
        #pragma unroll
        for (int off = 1; off <= 8; off <<= 1) {
            float om1 = __shfl_xor_sync(0xffffffffu, lm1[i], off);
            float om2 = __shfl_xor_sync(0xffffffffu, lm2[i], off);
            int   oi  = __shfl_xor_sync(0xffffffffu, li[i], off);
            float nm2 = fminf(fminf(lm2[i], om2), fmaxf(lm1[i], om1));
            if (om1 < lm1[i] || (om1 == lm1[i] && oi < li[i])) {
                lm1[i] = om1; li[i] = oi;
            }
            lm2[i] = nm2;
        }
        if (tx == 0) {
            int q = n0 + 4 * ty + i;
            g_idx[q] = li[i];
            g_dbest[q] = lm1[i];
            if (lm2[i] - lm1[i] <= FLAG_THRESH) {
                int s = atomicAdd(&g_fix_count, 1);
                g_fix_list[s] = q;
            }
        }
    }
}

// ---------------------------------------------------------------------------
// Fixup: exact fp32 recompute (R1 chain, proven rel_err 0.0) for near-ties.
// ---------------------------------------------------------------------------
__global__ void fixup_kernel(const float* __restrict__ z, const float* __restrict__ cb) {
    __shared__ float zq[256];
    __shared__ float rm[256];
    __shared__ int   rk[256];
    int cnt = g_fix_count;
    for (int it = blockIdx.x; it < cnt; it += gridDim.x) {
        int q = g_fix_list[it];
        int b = q >> 12, hw = q & 4095;
        zq[threadIdx.x] = z[((size_t)(b * 256 + threadIdx.x)) * 4096 + hw];
        __syncthreads();
        float A = 0.f;
        #pragma unroll 8
        for (int c = 0; c < 256; ++c) A = fmaf(zq[c], zq[c], A);
        float bm = FINF; int bk = 0;
        for (int t = 0; t < 4; ++t) {
            int k = threadIdx.x + 256 * t;
            const float* cr = cb + (size_t)k * 256;
            float dot = 0.f;
            #pragma unroll 8
            for (int c = 0; c < 256; ++c) dot = fmaf(zq[c], cr[c], dot);
            float d = fmaf(-2.f, dot, __fadd_rn(A, g_bnorm[k]));
            if (d < bm) { bm = d; bk = k; }          // k ascending per thread
        }
        rm[threadIdx.x] = bm; rk[threadIdx.x] = bk;
        __syncthreads();
        for (int s = 128; s > 0; s >>= 1) {
            if (threadIdx.x < s) {
                float v = rm[threadIdx.x + s]; int kk = rk[threadIdx.x + s];
                if (v < rm[threadIdx.x] ||
                    (v == rm[threadIdx.x] && kk < rk[threadIdx.x])) {
                    rm[threadIdx.x] = v; rk[threadIdx.x] = kk;
                }
            }
            __syncthreads();
        }
        if (threadIdx.x == 0) { g_idx[q] = rk[0]; g_dbest[q] = rm[0]; }
        __syncthreads();
    }
}

// ---------------------------------------------------------------------------
__global__ void write_zq(float* __restrict__ out, const float* __restrict__ z) {
    int p = blockIdx.x;               // b*256 + c
    int b = p >> 8, c = p & 255;
    const float* row  = g_cbT + (size_t)c * Kc;
    const int*   idxp = g_idx + b * HWc;
    const float* zp   = z + (size_t)p * HWc;
    float*       o    = out + (size_t)p * HWc;
    for (int hw = threadIdx.x; hw < HWc; hw += blockDim.x) {
        float zc = zp[hw];
        float zqv = row[idxp[hw]];
        o[hw] = __fadd_rn(zc, __fsub_rn(zqv, zc));
    }
}

__global__ void write_idx(float* __restrict__ out) {
    int n = blockIdx.x * blockDim.x + threadIdx.x;
    if (n < Nq) out[n] = (float)g_idx[n];
}

__global__ void loss_kernel(float* __restrict__ out) {
    __shared__ double sd[256];
    double s = 0.0;
    for (int i = threadIdx.x; i < Nq; i += 256) s += (double)g_dbest[i];
    sd[threadIdx.x] = s;
    __syncthreads();
    for (int r = 128; r > 0; r >>= 1) {
        if (threadIdx.x < r) sd[threadIdx.x] += sd[threadIdx.x + r];
        __syncthreads();
    }
    if (threadIdx.x == 0)
        out[0] = (float)(0.75 * sd[0] / (double)ZQ_ELEMS);
}

// ---------------------------------------------------------------------------
extern "C" void kernel_launch(void* const* d_in, const int* in_sizes, int n_in,
                              void* d_out, int out_size) {
    const float* z  = (const float*)d_in[0];   // [B,C,H,W] fp32
    const float* cb = (const float*)d_in[1];   // [K,C]     fp32
    float* out = (float*)d_out;

    cudaFuncSetAttribute(vq_dp4a, cudaFuncAttributeMaxDynamicSharedMemorySize, SMEM_BYTES);

    prep_kernel<<<Kc, 256>>>(cb);
    vq_dp4a<<<Nq / 64, 256, SMEM_BYTES>>>(z);
    fixup_kernel<<<4096, 256>>>(z, cb);
    write_zq<<<Bn * Cc, 256>>>(out, z);

    if (out_size >= ZQ_ELEMS + Nq)
        write_idx<<<Nq / 256, 256>>>(out + ZQ_ELEMS);
    if (out_size >= ZQ_ELEMS + Nq + 1)
        loss_kernel<<<1, 256>>>(out + ZQ_ELEMS + Nq);
    else if (out_size == ZQ_ELEMS + 1)
        loss_kernel<<<1, 256>>>(out + ZQ_ELEMS);
}

// round 9
// speedup vs baseline: 6.7971x; 6.7422x over previous
#include <cuda_runtime.h>
#include <cstdint>

// Problem constants
#define Bn  16
#define Cc  256
#define HWc 4096
#define Nq  65536
#define Kc  1024
#define ZQ_ELEMS 16777216
#define FINF __int_as_float(0x7f800000)

// -------------------------- device scratch --------------------------------
__device__ float g_cbT[Cc * Kc];    // codebook transposed [C][K]
__device__ float g_bnorm[Kc];       // ||c_k||^2 (R1 chain)
__device__ int   g_idx[Nq];
__device__ float g_dbest[Nq];

// -------------------------- smem layout (bytes) ----------------------------
#define OFF_ZT 0           // float zt[256][64]          65536
#define OFF_CS 65536       // float cs[2][16][128]       16384 (double buffer)
#define OFF_BN 81920       // float bn[1024]              4096
#define OFF_AS 86016       // float As[64]                 256
#define SMEM_BYTES 86272

// ---------------------------------------------------------------------------
// Prep: transpose codebook + per-code norms (identical chain to R1).
// ---------------------------------------------------------------------------
__global__ void prep_kernel(const float* __restrict__ cb) {
    int k = blockIdx.x, c = threadIdx.x;
    float v = cb[k * Cc + c];
    g_cbT[c * Kc + k] = v;
    __shared__ float sred[256];
    sred[c] = v * v;
    __syncthreads();
    for (int s = 128; s > 0; s >>= 1) {
        if (c < s) sred[c] += sred[c + s];
        __syncthreads();
    }
    if (c == 0) g_bnorm[k] = sred[0];
}

// ---------------------------------------------------------------------------
// Main: 1024 CTAs x 128 threads. Per CTA: 64 queries vs all 1024 codes.
// Thread (tx,ty): queries 8*ty..8*ty+7, codes 8*tx..8*tx+7 per 128-code tile.
// 8x8 fp32 register tile, c-ascending fmaf chain (bitwise == R1 == reference).
// Codebook chunks double-buffered (one __syncthreads per chunk).
// ---------------------------------------------------------------------------
__global__ void __launch_bounds__(128, 2) vq_main(const float* __restrict__ z) {
    extern __shared__ char smem[];
    float* zt = (float*)(smem + OFF_ZT);
    float* bn = (float*)(smem + OFF_BN);
    float* As = (float*)(smem + OFF_AS);
    float4* cs4 = (float4*)(smem + OFF_CS);        // 2 x 512 float4

    const int tid = threadIdx.x;
    const int tx = tid & 15, ty = tid >> 4;        // tx: code lane, ty: query lane
    const int n0 = blockIdx.x * 64;
    const float* zb = z + (size_t)(n0 >> 12) * (Cc * HWc) + (n0 & (HWc - 1));

    // ---- stage z [256 c][64 q] (coalesced float4) + bnorm ----
    const float4* zb4 = (const float4*)zb;
    float4* zt4w = (float4*)zt;
    #pragma unroll
    for (int i = 0; i < 32; ++i) {
        int c = ty + 8 * i;
        zt4w[c * 16 + tx] = zb4[(size_t)c * 1024 + tx];
    }
    #pragma unroll
    for (int i = 0; i < 8; ++i) bn[tid + 128 * i] = g_bnorm[tid + 128 * i];
    __syncthreads();

    // ---- norms: exact R1 sequential fmaf chain over c ascending ----
    if (tid < 64) {
        float a = 0.f;
        #pragma unroll 8
        for (int c = 0; c < Cc; ++c) {
            float v = zt[c * 64 + tid];
            a = fmaf(v, v, a);
        }
        As[tid] = a;
    }
    __syncthreads();

    float Aqv[8];
    #pragma unroll
    for (int qi = 0; qi < 8; ++qi) Aqv[qi] = As[8 * ty + qi];

    float mv[8]; int mi[8];
    #pragma unroll
    for (int qi = 0; qi < 8; ++qi) { mv[qi] = FINF; mi[qi] = 0; }

    const float4* cbT4 = (const float4*)g_cbT;     // row c = 256 float4
    const float4* zt4 = (const float4*)zt;

    for (int kt = 0; kt < 8; ++kt) {
        // ---- prefetch + store chunk 0 ----
        float4 pf[4];
        #pragma unroll
        for (int j = 0; j < 4; ++j) {
            int f = tid + 128 * j;
            pf[j] = cbT4[(size_t)(f >> 5) * 256 + kt * 32 + (f & 31)];
        }
        #pragma unroll
        for (int j = 0; j < 4; ++j) {
            int f = tid + 128 * j;
            cs4[(f >> 5) * 32 + (f & 31)] = pf[j];
        }
        __syncthreads();

        float acc[8][8];
        #pragma unroll
        for (int qi = 0; qi < 8; ++qi)
            #pragma unroll
            for (int kj = 0; kj < 8; ++kj) acc[qi][kj] = 0.f;

        for (int cc = 0; cc < 16; ++cc) {
            const float4* cur = cs4 + (cc & 1) * 512;
            if (cc < 15) {                          // prefetch next chunk
                #pragma unroll
                for (int j = 0; j < 4; ++j) {
                    int f = tid + 128 * j;
                    pf[j] = cbT4[(size_t)((cc + 1) * 16 + (f >> 5)) * 256 +
                                 kt * 32 + (f & 31)];
                }
            }
            #pragma unroll
            for (int ck = 0; ck < 16; ++ck) {
                const int crow = cc * 16 + ck;
                float4 a0 = zt4[crow * 16 + 2 * ty];
                float4 a1 = zt4[crow * 16 + 2 * ty + 1];
                float4 b0 = cur[ck * 32 + 2 * tx];
                float4 b1 = cur[ck * 32 + 2 * tx + 1];
                float av[8] = {a0.x, a0.y, a0.z, a0.w, a1.x, a1.y, a1.z, a1.w};
                float bv[8] = {b0.x, b0.y, b0.z, b0.w, b1.x, b1.y, b1.z, b1.w};
                #pragma unroll
                for (int qi = 0; qi < 8; ++qi)
                    #pragma unroll
                    for (int kj = 0; kj < 8; ++kj)
                        acc[qi][kj] = fmaf(av[qi], bv[kj], acc[qi][kj]);
            }
            if (cc < 15) {                          // store into other buffer
                float4* nxt = cs4 + ((cc + 1) & 1) * 512;
                #pragma unroll
                for (int j = 0; j < 4; ++j) {
                    int f = tid + 128 * j;
                    nxt[(f >> 5) * 32 + (f & 31)] = pf[j];
                }
                __syncthreads();
            }
        }

        // ---- epilogue: distances + running argmin (k ascending) ----
        float4 bn0 = ((const float4*)bn)[kt * 32 + 2 * tx];
        float4 bn1 = ((const float4*)bn)[kt * 32 + 2 * tx + 1];
        float bnv[8] = {bn0.x, bn0.y, bn0.z, bn0.w, bn1.x, bn1.y, bn1.z, bn1.w};
        #pragma unroll
        for (int qi = 0; qi < 8; ++qi)
            #pragma unroll
            for (int kj = 0; kj < 8; ++kj) {
                float d = fmaf(-2.f, acc[qi][kj], __fadd_rn(Aqv[qi], bnv[kj]));
                if (d < mv[qi]) {                   // strict < keeps lowest k
                    mv[qi] = d;
                    mi[qi] = kt * 128 + 8 * tx + kj;
                }
            }
    }

    // ---- reduce across the 16 tx lanes (in-warp), lowest-k tie-break ----
    #pragma unroll
    for (int qi = 0; qi < 8; ++qi) {
        #pragma unroll
        for (int off = 1; off <= 8; off <<= 1) {
            float om = __shfl_xor_sync(0xffffffffu, mv[qi], off);
            int   oi = __shfl_xor_sync(0xffffffffu, mi[qi], off);
            if (om < mv[qi] || (om == mv[qi] && oi < mi[qi])) {
                mv[qi] = om; mi[qi] = oi;
            }
        }
        if (tx == 0) {
            int q = n0 + 8 * ty + qi;
            g_idx[q] = mi[qi];
            g_dbest[q] = mv[qi];
        }
    }
}

// ---------------------------------------------------------------------------
// Writer: zq_st in NCHW. out = fl(zc + fl(zq - zc)) (reference rounding).
// ---------------------------------------------------------------------------
__global__ void write_zq(float* __restrict__ out, const float* __restrict__ z) {
    int p = blockIdx.x;               // b*256 + c
    int b = p >> 8, c = p & 255;
    const float* row  = g_cbT + (size_t)c * Kc;
    const int*   idxp = g_idx + b * HWc;
    const float* zp   = z + (size_t)p * HWc;
    float*       o    = out + (size_t)p * HWc;
    for (int hw = threadIdx.x; hw < HWc; hw += blockDim.x) {
        float zc = zp[hw];
        float zqv = row[idxp[hw]];
        o[hw] = __fadd_rn(zc, __fsub_rn(zqv, zc));
    }
}

__global__ void write_idx(float* __restrict__ out) {
    int n = blockIdx.x * blockDim.x + threadIdx.x;
    if (n < Nq) out[n] = (float)g_idx[n];
}

// loss = (1 - BETA) * mean((zq - zc)^2)
__global__ void loss_kernel(float* __restrict__ out) {
    __shared__ double sd[256];
    double s = 0.0;
    for (int i = threadIdx.x; i < Nq; i += 256) s += (double)g_dbest[i];
    sd[threadIdx.x] = s;
    __syncthreads();
    for (int r = 128; r > 0; r >>= 1) {
        if (threadIdx.x < r) sd[threadIdx.x] += sd[threadIdx.x + r];
        __syncthreads();
    }
    if (threadIdx.x == 0)
        out[0] = (float)(0.75 * sd[0] / (double)ZQ_ELEMS);
}

// ---------------------------------------------------------------------------
extern "C" void kernel_launch(void* const* d_in, const int* in_sizes, int n_in,
                              void* d_out, int out_size) {
    const float* z  = (const float*)d_in[0];   // [B,C,H,W] fp32
    const float* cb = (const float*)d_in[1];   // [K,C]     fp32
    float* out = (float*)d_out;

    cudaFuncSetAttribute(vq_main, cudaFuncAttributeMaxDynamicSharedMemorySize, SMEM_BYTES);

    prep_kernel<<<Kc, 256>>>(cb);
    vq_main<<<Nq / 64, 128, SMEM_BYTES>>>(z);
    write_zq<<<Bn * Cc, 256>>>(out, z);

    if (out_size >= ZQ_ELEMS + Nq)
        write_idx<<<Nq / 256, 256>>>(out + ZQ_ELEMS);
    if (out_size >= ZQ_ELEMS + Nq + 1)
        loss_kernel<<<1, 256>>>(out + ZQ_ELEMS + Nq);
    else if (out_size == ZQ_ELEMS + 1)
        loss_kernel<<<1, 256>>>(out + ZQ_ELEMS);
}

// round 10
// speedup vs baseline: 7.0764x; 1.0411x over previous
#include <cuda_runtime.h>
#include <cstdint>

// Problem constants
#define Bn  16
#define Cc  256
#define HWc 4096
#define Nq  65536
#define Kc  1024
#define ZQ_ELEMS 16777216
#define FINF __int_as_float(0x7f800000)

// -------------------------- device scratch --------------------------------
__device__ float g_cbT[Cc * Kc];    // codebook transposed [C][K]
__device__ float g_bnorm[Kc];       // ||c_k||^2 (R1 chain)
__device__ int   g_idx[Nq];
__device__ float g_dbest[Nq];

// -------------------------- smem layout (bytes) ----------------------------
#define OFF_ZT 0           // float zt[256][64]          65536
#define OFF_CS 65536       // float cs[2][32][128]       32768 (double buffer)
#define OFF_BN 98304       // float bn[1024]              4096
#define OFF_AS 102400      // float As[64]                 256
#define SMEM_BYTES 102656

// ---------------------------------------------------------------------------
// Prep: transpose codebook + per-code norms (identical chain to R1).
// ---------------------------------------------------------------------------
__global__ void prep_kernel(const float* __restrict__ cb) {
    int k = blockIdx.x, c = threadIdx.x;
    float v = cb[k * Cc + c];
    g_cbT[c * Kc + k] = v;
    __shared__ float sred[256];
    sred[c] = v * v;
    __syncthreads();
    for (int s = 128; s > 0; s >>= 1) {
        if (c < s) sred[c] += sred[c + s];
        __syncthreads();
    }
    if (c == 0) g_bnorm[k] = sred[0];
}

// ---------------------------------------------------------------------------
// Main: 1024 CTAs x 128 threads. Per CTA: 64 queries vs all 1024 codes.
// Thread (tx,ty): queries 8*ty..8*ty+7, codes 8*tx..8*tx+7 per 128-code tile.
// 8x8 fp32 register tile, c-ascending fmaf chain (bitwise == R1 == reference).
// 32-row codebook chunks, double-buffered: one __syncthreads per chunk.
// ---------------------------------------------------------------------------
__global__ void __launch_bounds__(128, 2) vq_main(const float* __restrict__ z) {
    extern __shared__ char smem[];
    float* zt = (float*)(smem + OFF_ZT);
    float* bn = (float*)(smem + OFF_BN);
    float* As = (float*)(smem + OFF_AS);
    float4* cs4 = (float4*)(smem + OFF_CS);        // 2 x 1024 float4

    const int tid = threadIdx.x;
    const int tx = tid & 15, ty = tid >> 4;        // tx: code lane, ty: query lane
    const int n0 = blockIdx.x * 64;
    const float* zb = z + (size_t)(n0 >> 12) * (Cc * HWc) + (n0 & (HWc - 1));

    // ---- stage z [256 c][64 q] (coalesced float4) + bnorm ----
    const float4* zb4 = (const float4*)zb;
    float4* zt4w = (float4*)zt;
    #pragma unroll
    for (int i = 0; i < 32; ++i) {
        int c = ty + 8 * i;
        zt4w[c * 16 + tx] = zb4[(size_t)c * 1024 + tx];
    }
    #pragma unroll
    for (int i = 0; i < 8; ++i) bn[tid + 128 * i] = g_bnorm[tid + 128 * i];
    __syncthreads();

    // ---- norms: exact R1 sequential fmaf chain over c ascending ----
    if (tid < 64) {
        float a = 0.f;
        #pragma unroll 8
        for (int c = 0; c < Cc; ++c) {
            float v = zt[c * 64 + tid];
            a = fmaf(v, v, a);
        }
        As[tid] = a;
    }
    __syncthreads();

    float Aqv[8];
    #pragma unroll
    for (int qi = 0; qi < 8; ++qi) Aqv[qi] = As[8 * ty + qi];

    float mv[8]; int mi[8];
    #pragma unroll
    for (int qi = 0; qi < 8; ++qi) { mv[qi] = FINF; mi[qi] = 0; }

    const float4* cbT4 = (const float4*)g_cbT;     // row c = 256 float4
    const float4* zt4 = (const float4*)zt;

    for (int kt = 0; kt < 8; ++kt) {
        // ---- prefetch + store chunk 0 (32 c-rows x 128 codes) ----
        float4 pf[8];
        #pragma unroll
        for (int j = 0; j < 8; ++j) {
            int f = tid + 128 * j;                 // 0..1023
            pf[j] = cbT4[(size_t)(f >> 5) * 256 + kt * 32 + (f & 31)];
        }
        #pragma unroll
        for (int j = 0; j < 8; ++j) {
            int f = tid + 128 * j;
            cs4[(f >> 5) * 32 + (f & 31)] = pf[j];
        }
        __syncthreads();

        float acc[8][8];
        #pragma unroll
        for (int qi = 0; qi < 8; ++qi)
            #pragma unroll
            for (int kj = 0; kj < 8; ++kj) acc[qi][kj] = 0.f;

        for (int cc = 0; cc < 8; ++cc) {           // 8 chunks x 32 c-rows
            const float4* cur = cs4 + (cc & 1) * 1024;
            if (cc < 7) {                          // prefetch next chunk
                #pragma unroll
                for (int j = 0; j < 8; ++j) {
                    int f = tid + 128 * j;
                    pf[j] = cbT4[(size_t)((cc + 1) * 32 + (f >> 5)) * 256 +
                                 kt * 32 + (f & 31)];
                }
            }
            #pragma unroll
            for (int ck = 0; ck < 32; ++ck) {
                const int crow = cc * 32 + ck;
                float4 a0 = zt4[crow * 16 + 2 * ty];
                float4 a1 = zt4[crow * 16 + 2 * ty + 1];
                float4 b0 = cur[ck * 32 + 2 * tx];
                float4 b1 = cur[ck * 32 + 2 * tx + 1];
                float av[8] = {a0.x, a0.y, a0.z, a0.w, a1.x, a1.y, a1.z, a1.w};
                float bv[8] = {b0.x, b0.y, b0.z, b0.w, b1.x, b1.y, b1.z, b1.w};
                #pragma unroll
                for (int qi = 0; qi < 8; ++qi)
                    #pragma unroll
                    for (int kj = 0; kj < 8; ++kj)
                        acc[qi][kj] = fmaf(av[qi], bv[kj], acc[qi][kj]);
            }
            if (cc < 7) {                          // store into other buffer
                float4* nxt = cs4 + ((cc + 1) & 1) * 1024;
                #pragma unroll
                for (int j = 0; j < 8; ++j) {
                    int f = tid + 128 * j;
                    nxt[(f >> 5) * 32 + (f & 31)] = pf[j];
                }
                __syncthreads();
            }
        }

        // ---- epilogue: distances + running argmin (k ascending) ----
        float4 bn0 = ((const float4*)bn)[kt * 32 + 2 * tx];
        float4 bn1 = ((const float4*)bn)[kt * 32 + 2 * tx + 1];
        float bnv[8] = {bn0.x, bn0.y, bn0.z, bn0.w, bn1.x, bn1.y, bn1.z, bn1.w};
        #pragma unroll
        for (int qi = 0; qi < 8; ++qi)
            #pragma unroll
            for (int kj = 0; kj < 8; ++kj) {
                float d = fmaf(-2.f, acc[qi][kj], __fadd_rn(Aqv[qi], bnv[kj]));
                if (d < mv[qi]) {                   // strict < keeps lowest k
                    mv[qi] = d;
                    mi[qi] = kt * 128 + 8 * tx + kj;
                }
            }
        __syncthreads();   // before next kt reuses cs buffer 0
    }

    // ---- reduce across the 16 tx lanes (in-warp), lowest-k tie-break ----
    #pragma unroll
    for (int qi = 0; qi < 8; ++qi) {
        #pragma unroll
        for (int off = 1; off <= 8; off <<= 1) {
            float om = __shfl_xor_sync(0xffffffffu, mv[qi], off);
            int   oi = __shfl_xor_sync(0xffffffffu, mi[qi], off);
            if (om < mv[qi] || (om == mv[qi] && oi < mi[qi])) {
                mv[qi] = om; mi[qi] = oi;
            }
        }
        if (tx == 0) {
            int q = n0 + 8 * ty + qi;
            g_idx[q] = mi[qi];
            g_dbest[q] = mv[qi];
        }
    }
}

// ---------------------------------------------------------------------------
// Fused epilogue: blocks 0..4095 write zq_st (float4/int4 vectorized, exact
// reference rounding); blocks 4096..4351 write idx-as-float; block 4352 loss.
// ---------------------------------------------------------------------------
__global__ void __launch_bounds__(256) epilogue_kernel(
        float* __restrict__ out, const float* __restrict__ z,
        int has_idx, int loss_off) {
    int p = blockIdx.x;
    if (p < 4096) {
        int b = p >> 8, c = p & 255;
        const float* row = g_cbT + (size_t)c * Kc;        // 4KB, L1-hot
        const int4*  id4 = (const int4*)(g_idx + b * HWc);
        const float4* zp4 = (const float4*)(z + (size_t)p * HWc);
        float4* o4 = (float4*)(out + (size_t)p * HWc);
        #pragma unroll
        for (int i = 0; i < 4; ++i) {
            int v = threadIdx.x + 256 * i;
            float4 zc = zp4[v];
            int4 id = id4[v];
            float4 r;
            r.x = __fadd_rn(zc.x, __fsub_rn(row[id.x], zc.x));
            r.y = __fadd_rn(zc.y, __fsub_rn(row[id.y], zc.y));
            r.z = __fadd_rn(zc.z, __fsub_rn(row[id.z], zc.z));
            r.w = __fadd_rn(zc.w, __fsub_rn(row[id.w], zc.w));
            o4[v] = r;
        }
    } else if (p < 4352) {
        if (has_idx) {
            int n = (p - 4096) * 256 + threadIdx.x;
            out[ZQ_ELEMS + n] = (float)g_idx[n];
        }
    } else {
        if (loss_off >= 0) {
            __shared__ double sd[256];
            double s = 0.0;
            for (int i = threadIdx.x; i < Nq; i += 256) s += (double)g_dbest[i];
            sd[threadIdx.x] = s;
            __syncthreads();
            for (int r = 128; r > 0; r >>= 1) {
                if (threadIdx.x < r) sd[threadIdx.x] += sd[threadIdx.x + r];
                __syncthreads();
            }
            if (threadIdx.x == 0)
                out[loss_off] = (float)(0.75 * sd[0] / (double)ZQ_ELEMS);
        }
    }
}

// ---------------------------------------------------------------------------
extern "C" void kernel_launch(void* const* d_in, const int* in_sizes, int n_in,
                              void* d_out, int out_size) {
    const float* z  = (const float*)d_in[0];   // [B,C,H,W] fp32
    const float* cb = (const float*)d_in[1];   // [K,C]     fp32
    float* out = (float*)d_out;

    cudaFuncSetAttribute(vq_main, cudaFuncAttributeMaxDynamicSharedMemorySize, SMEM_BYTES);

    int has_idx = (out_size >= ZQ_ELEMS + Nq) ? 1 : 0;
    int loss_off = -1;
    if (out_size >= ZQ_ELEMS + Nq + 1) loss_off = ZQ_ELEMS + Nq;
    else if (out_size == ZQ_ELEMS + 1) loss_off = ZQ_ELEMS;

    prep_kernel<<<Kc, 256>>>(cb);
    vq_main<<<Nq / 64, 128, SMEM_BYTES>>>(z);
    epilogue_kernel<<<4353, 256>>>(out, z, has_idx, loss_off);
}

// round 14
// speedup vs baseline: 7.7322x; 1.0927x over previous
#include <cuda_runtime.h>
#include <cstdint>

// Problem constants
#define Bn  16
#define Cc  256
#define HWc 4096
#define Nq  65536
#define Kc  1024
#define ZQ_ELEMS 16777216
#define FINF __int_as_float(0x7f800000)

// -------------------------- device scratch --------------------------------
__device__ float g_cbT[Cc * Kc];    // codebook transposed [C][K]
__device__ float g_bnorm[Kc];       // ||c_k||^2 (R1 chain)
__device__ float g_d2[2 * Nq];      // per-half best distance
__device__ int   g_k2[2 * Nq];      // per-half best index
__device__ int   g_idx[Nq];
__device__ float g_dbest[Nq];

// -------------------------- smem layout (bytes) ----------------------------
#define OFF_ZT 0           // float zt[256][64]          65536
#define OFF_CS 65536       // float cs[2][32][128]       32768 (double buffer)
#define OFF_BN 98304       // float bn[512]               2048
#define OFF_AS 100352      // float As[64]                 256
#define SMEM_BYTES 100608

// ---------------------------------------------------------------------------
// Prep: transpose codebook + per-code norms (identical chain to R1).
// ---------------------------------------------------------------------------
__global__ void prep_kernel(const float* __restrict__ cb) {
    int k = blockIdx.x, c = threadIdx.x;
    float v = cb[k * Cc + c];
    g_cbT[c * Kc + k] = v;
    __shared__ float sred[256];
    sred[c] = v * v;
    __syncthreads();
    for (int s = 128; s > 0; s >>= 1) {
        if (c < s) sred[c] += sred[c + s];
        __syncthreads();
    }
    if (c == 0) g_bnorm[k] = sred[0];
}

// ---------------------------------------------------------------------------
// Main: 2048 CTAs x 128 threads. CTA = (64-query tile) x (512-code half).
// bid: tile = bid >> 1, half = bid & 1 (codes half*512 .. half*512+511).
// Thread (tx,ty): queries 8*ty..8*ty+7, codes 8*tx..8*tx+7 per 128-code tile.
// 8x8 fp32 register tile, c-ascending fmaf chain (bitwise == R1 == reference).
// ---------------------------------------------------------------------------
__global__ void __launch_bounds__(128, 2) vq_main(const float* __restrict__ z) {
    extern __shared__ char smem[];
    float* zt = (float*)(smem + OFF_ZT);
    float* bn = (float*)(smem + OFF_BN);
    float* As = (float*)(smem + OFF_AS);
    float4* cs4 = (float4*)(smem + OFF_CS);        // 2 x 1024 float4

    const int tid = threadIdx.x;
    const int tx = tid & 15, ty = tid >> 4;        // tx: code lane, ty: query lane
    const int tile = blockIdx.x >> 1;
    const int half = blockIdx.x & 1;
    const int k0g  = half * 512;                   // code base for this CTA
    const int n0 = tile * 64;
    const float* zb = z + (size_t)(n0 >> 12) * (Cc * HWc) + (n0 & (HWc - 1));

    // ---- stage z [256 c][64 q] (coalesced float4) + bnorm half ----
    const float4* zb4 = (const float4*)zb;
    float4* zt4w = (float4*)zt;
    #pragma unroll
    for (int i = 0; i < 32; ++i) {
        int c = ty + 8 * i;
        zt4w[c * 16 + tx] = zb4[(size_t)c * 1024 + tx];
    }
    #pragma unroll
    for (int i = 0; i < 4; ++i) bn[tid + 128 * i] = g_bnorm[k0g + tid + 128 * i];
    __syncthreads();

    // ---- norms: exact R1 sequential fmaf chain over c ascending ----
    if (tid < 64) {
        float a = 0.f;
        #pragma unroll 8
        for (int c = 0; c < Cc; ++c) {
            float v = zt[c * 64 + tid];
            a = fmaf(v, v, a);
        }
        As[tid] = a;
    }
    __syncthreads();

    float Aqv[8];
    #pragma unroll
    for (int qi = 0; qi < 8; ++qi) Aqv[qi] = As[8 * ty + qi];

    float mv[8]; int mi[8];
    #pragma unroll
    for (int qi = 0; qi < 8; ++qi) { mv[qi] = FINF; mi[qi] = 0; }

    const float4* cbT4 = (const float4*)g_cbT;     // row c = 256 float4
    const float4* zt4 = (const float4*)zt;

    for (int kt = 0; kt < 4; ++kt) {
        const int ktg = half * 4 + kt;             // global 128-code tile id
        // ---- prefetch + store chunk 0 (32 c-rows x 128 codes) ----
        float4 pf[8];
        #pragma unroll
        for (int j = 0; j < 8; ++j) {
            int f = tid + 128 * j;                 // 0..1023
            pf[j] = cbT4[(size_t)(f >> 5) * 256 + ktg * 32 + (f & 31)];
        }
        #pragma unroll
        for (int j = 0; j < 8; ++j) {
            int f = tid + 128 * j;
            cs4[(f >> 5) * 32 + (f & 31)] = pf[j];
        }
        __syncthreads();

        float acc[8][8];
        #pragma unroll
        for (int qi = 0; qi < 8; ++qi)
            #pragma unroll
            for (int kj = 0; kj < 8; ++kj) acc[qi][kj] = 0.f;

        for (int cc = 0; cc < 8; ++cc) {           // 8 chunks x 32 c-rows
            const float4* cur = cs4 + (cc & 1) * 1024;
            if (cc < 7) {                          // prefetch next chunk
                #pragma unroll
                for (int j = 0; j < 8; ++j) {
                    int f = tid + 128 * j;
                    pf[j] = cbT4[(size_t)((cc + 1) * 32 + (f >> 5)) * 256 +
                                 ktg * 32 + (f & 31)];
                }
            }
            #pragma unroll
            for (int ck = 0; ck < 32; ++ck) {
                const int crow = cc * 32 + ck;
                float4 a0 = zt4[crow * 16 + 2 * ty];
                float4 a1 = zt4[crow * 16 + 2 * ty + 1];
                float4 b0 = cur[ck * 32 + 2 * tx];
                float4 b1 = cur[ck * 32 + 2 * tx + 1];
                float av[8] = {a0.x, a0.y, a0.z, a0.w, a1.x, a1.y, a1.z, a1.w};
                float bv[8] = {b0.x, b0.y, b0.z, b0.w, b1.x, b1.y, b1.z, b1.w};
                #pragma unroll
                for (int qi = 0; qi < 8; ++qi)
                    #pragma unroll
                    for (int kj = 0; kj < 8; ++kj)
                        acc[qi][kj] = fmaf(av[qi], bv[kj], acc[qi][kj]);
            }
            if (cc < 7) {                          // store into other buffer
                float4* nxt = cs4 + ((cc + 1) & 1) * 1024;
                #pragma unroll
                for (int j = 0; j < 8; ++j) {
                    int f = tid + 128 * j;
                    nxt[(f >> 5) * 32 + (f & 31)] = pf[j];
                }
                __syncthreads();
            }
        }

        // ---- epilogue: distances + running argmin (k ascending) ----
        float4 bn0 = ((const float4*)bn)[kt * 32 + 2 * tx];
        float4 bn1 = ((const float4*)bn)[kt * 32 + 2 * tx + 1];
        float bnv[8] = {bn0.x, bn0.y, bn0.z, bn0.w, bn1.x, bn1.y, bn1.z, bn1.w};
        #pragma unroll
        for (int qi = 0; qi < 8; ++qi)
            #pragma unroll
            for (int kj = 0; kj < 8; ++kj) {
                float d = fmaf(-2.f, acc[qi][kj], __fadd_rn(Aqv[qi], bnv[kj]));
                if (d < mv[qi]) {                   // strict < keeps lowest k
                    mv[qi] = d;
                    mi[qi] = k0g + kt * 128 + 8 * tx + kj;
                }
            }
        __syncthreads();   // before next kt reuses cs buffer 0
    }

    // ---- reduce across the 16 tx lanes (in-warp), lowest-k tie-break ----
    #pragma unroll
    for (int qi = 0; qi < 8; ++qi) {
        #pragma unroll
        for (int off = 1; off <= 8; off <<= 1) {
            float om = __shfl_xor_sync(0xffffffffu, mv[qi], off);
            int   oi = __shfl_xor_sync(0xffffffffu, mi[qi], off);
            if (om < mv[qi] || (om == mv[qi] && oi < mi[qi])) {
                mv[qi] = om; mi[qi] = oi;
            }
        }
        if (tx == 0) {
            int q = n0 + 8 * ty + qi;
            g_d2[half * Nq + q] = mv[qi];
            g_k2[half * Nq + q] = mi[qi];
        }
    }
}

// ---------------------------------------------------------------------------
// Merge the two code-half candidates. Half-0 indices are always lower, so a
// tie (equal d) keeps half 0 — matches jnp.argmin first occurrence.
// ---------------------------------------------------------------------------
__global__ void merge_kernel() {
    int q = blockIdx.x * blockDim.x + threadIdx.x;
    float d0 = g_d2[q], d1 = g_d2[Nq + q];
    int   k0 = g_k2[q], k1 = g_k2[Nq + q];
    if (d1 < d0) { d0 = d1; k0 = k1; }
    g_idx[q] = k0;
    g_dbest[q] = d0;
}

// ---------------------------------------------------------------------------
// Fused epilogue: blocks 0..4095 write zq_st (vectorized, exact reference
// rounding); blocks 4096..4351 write idx-as-float; block 4352 loss.
// ---------------------------------------------------------------------------
__global__ void __launch_bounds__(256) epilogue_kernel(
        float* __restrict__ out, const float* __restrict__ z,
        int has_idx, int loss_off) {
    int p = blockIdx.x;
    if (p < 4096) {
        int b = p >> 8, c = p & 255;
        const float* row = g_cbT + (size_t)c * Kc;        // 4KB, L1-hot
        const int4*  id4 = (const int4*)(g_idx + b * HWc);
        const float4* zp4 = (const float4*)(z + (size_t)p * HWc);
        float4* o4 = (float4*)(out + (size_t)p * HWc);
        #pragma unroll
        for (int i = 0; i < 4; ++i) {
            int v = threadIdx.x + 256 * i;
            float4 zc = zp4[v];
            int4 id = id4[v];
            float4 r;
            r.x = __fadd_rn(zc.x, __fsub_rn(row[id.x], zc.x));
            r.y = __fadd_rn(zc.y, __fsub_rn(row[id.y], zc.y));
            r.z = __fadd_rn(zc.z, __fsub_rn(row[id.z], zc.z));
            r.w = __fadd_rn(zc.w, __fsub_rn(row[id.w], zc.w));
            o4[v] = r;
        }
    } else if (p < 4352) {
        if (has_idx) {
            int n = (p - 4096) * 256 + threadIdx.x;
            out[ZQ_ELEMS + n] = (float)g_idx[n];
        }
    } else {
        if (loss_off >= 0) {
            __shared__ double sd[256];
            double s = 0.0;
            for (int i = threadIdx.x; i < Nq; i += 256) s += (double)g_dbest[i];
            sd[threadIdx.x] = s;
            __syncthreads();
            for (int r = 128; r > 0; r >>= 1) {
                if (threadIdx.x < r) sd[threadIdx.x] += sd[threadIdx.x + r];
                __syncthreads();
            }
            if (threadIdx.x == 0)
                out[loss_off] = (float)(0.75 * sd[0] / (double)ZQ_ELEMS);
        }
    }
}

// ---------------------------------------------------------------------------
extern "C" void kernel_launch(void* const* d_in, const int* in_sizes, int n_in,
                              void* d_out, int out_size) {
    const float* z  = (const float*)d_in[0];   // [B,C,H,W] fp32
    const float* cb = (const float*)d_in[1];   // [K,C]     fp32
    float* out = (float*)d_out;

    cudaFuncSetAttribute(vq_main, cudaFuncAttributeMaxDynamicSharedMemorySize, SMEM_BYTES);

    int has_idx = (out_size >= ZQ_ELEMS + Nq) ? 1 : 0;
    int loss_off = -1;
    if (out_size >= ZQ_ELEMS + Nq + 1) loss_off = ZQ_ELEMS + Nq;
    else if (out_size == ZQ_ELEMS + 1) loss_off = ZQ_ELEMS;

    prep_kernel<<<Kc, 256>>>(cb);
    vq_main<<<2 * (Nq / 64), 128, SMEM_BYTES>>>(z);
    merge_kernel<<<Nq / 256, 256>>>();
    epilogue_kernel<<<4353, 256>>>(out, z, has_idx, loss_off);
}

// round 15
// speedup vs baseline: 8.1284x; 1.0512x over previous
#include <cuda_runtime.h>
#include <cstdint>

// Problem constants
#define Bn  16
#define Cc  256
#define HWc 4096
#define Nq  65536
#define Kc  1024
#define ZQ_ELEMS 16777216
#define FINF __int_as_float(0x7f800000)

// -------------------------- device scratch --------------------------------
__device__ float  g_cbT[Cc * Kc];    // codebook transposed [C][K]
__device__ float  g_bnorm[Kc];       // ||c_k||^2 (R1 chain)
__device__ float  g_d2[2 * Nq];      // per-half best distance
__device__ int    g_k2[2 * Nq];      // per-half best index
__device__ int    g_idx[Nq];
__device__ double g_lpart[256];      // per-merge-block loss partial sums

// -------------------------- smem layout (bytes) ----------------------------
#define OFF_ZT 0           // float zt[256][64]          65536
#define OFF_CS 65536       // float cs[2][32][128]       32768 (double buffer)
#define OFF_BN 98304       // float bn[512]               2048
#define OFF_AS 100352      // float As[64]                 256
#define SMEM_BYTES 100608

// ---------------------------------------------------------------------------
// Prep: transpose codebook + per-code norms (identical chain to R1).
// ---------------------------------------------------------------------------
__global__ void prep_kernel(const float* __restrict__ cb) {
    int k = blockIdx.x, c = threadIdx.x;
    float v = cb[k * Cc + c];
    g_cbT[c * Kc + k] = v;
    __shared__ float sred[256];
    sred[c] = v * v;
    __syncthreads();
    for (int s = 128; s > 0; s >>= 1) {
        if (c < s) sred[c] += sred[c + s];
        __syncthreads();
    }
    if (c == 0) g_bnorm[k] = sred[0];
}

// ---------------------------------------------------------------------------
// Main: 2048 CTAs x 128 threads. CTA = (64-query tile) x (512-code half).
// bid: tile = bid >> 1, half = bid & 1 (codes half*512 .. half*512+511).
// Thread (tx,ty): queries 8*ty..8*ty+7, codes 8*tx..8*tx+7 per 128-code tile.
// 8x8 fp32 register tile, c-ascending fmaf chain (bitwise == R1 == reference).
// ---------------------------------------------------------------------------
__global__ void __launch_bounds__(128, 2) vq_main(const float* __restrict__ z) {
    extern __shared__ char smem[];
    float* zt = (float*)(smem + OFF_ZT);
    float* bn = (float*)(smem + OFF_BN);
    float* As = (float*)(smem + OFF_AS);
    float4* cs4 = (float4*)(smem + OFF_CS);        // 2 x 1024 float4

    const int tid = threadIdx.x;
    const int tx = tid & 15, ty = tid >> 4;        // tx: code lane, ty: query lane
    const int tile = blockIdx.x >> 1;
    const int half = blockIdx.x & 1;
    const int k0g  = half * 512;                   // code base for this CTA
    const int n0 = tile * 64;
    const float* zb = z + (size_t)(n0 >> 12) * (Cc * HWc) + (n0 & (HWc - 1));

    // ---- stage z [256 c][64 q] (coalesced float4) + bnorm half ----
    const float4* zb4 = (const float4*)zb;
    float4* zt4w = (float4*)zt;
    #pragma unroll
    for (int i = 0; i < 32; ++i) {
        int c = ty + 8 * i;
        zt4w[c * 16 + tx] = zb4[(size_t)c * 1024 + tx];
    }
    #pragma unroll
    for (int i = 0; i < 4; ++i) bn[tid + 128 * i] = g_bnorm[k0g + tid + 128 * i];
    __syncthreads();

    // ---- norms: exact R1 sequential fmaf chain over c ascending ----
    if (tid < 64) {
        float a = 0.f;
        #pragma unroll 8
        for (int c = 0; c < Cc; ++c) {
            float v = zt[c * 64 + tid];
            a = fmaf(v, v, a);
        }
        As[tid] = a;
    }
    __syncthreads();

    float Aqv[8];
    #pragma unroll
    for (int qi = 0; qi < 8; ++qi) Aqv[qi] = As[8 * ty + qi];

    float mv[8]; int mi[8];
    #pragma unroll
    for (int qi = 0; qi < 8; ++qi) { mv[qi] = FINF; mi[qi] = 0; }

    const float4* cbT4 = (const float4*)g_cbT;     // row c = 256 float4
    const float4* zt4 = (const float4*)zt;

    for (int kt = 0; kt < 4; ++kt) {
        const int ktg = half * 4 + kt;             // global 128-code tile id
        // ---- prefetch + store chunk 0 (32 c-rows x 128 codes) ----
        float4 pf[8];
        #pragma unroll
        for (int j = 0; j < 8; ++j) {
            int f = tid + 128 * j;                 // 0..1023
            pf[j] = cbT4[(size_t)(f >> 5) * 256 + ktg * 32 + (f & 31)];
        }
        #pragma unroll
        for (int j = 0; j < 8; ++j) {
            int f = tid + 128 * j;
            cs4[(f >> 5) * 32 + (f & 31)] = pf[j];
        }
        __syncthreads();

        float acc[8][8];
        #pragma unroll
        for (int qi = 0; qi < 8; ++qi)
            #pragma unroll
            for (int kj = 0; kj < 8; ++kj) acc[qi][kj] = 0.f;

        for (int cc = 0; cc < 8; ++cc) {           // 8 chunks x 32 c-rows
            const float4* cur = cs4 + (cc & 1) * 1024;
            if (cc < 7) {                          // prefetch next chunk
                #pragma unroll
                for (int j = 0; j < 8; ++j) {
                    int f = tid + 128 * j;
                    pf[j] = cbT4[(size_t)((cc + 1) * 32 + (f >> 5)) * 256 +
                                 ktg * 32 + (f & 31)];
                }
            }
            #pragma unroll
            for (int ck = 0; ck < 32; ++ck) {
                const int crow = cc * 32 + ck;
                float4 a0 = zt4[crow * 16 + 2 * ty];
                float4 a1 = zt4[crow * 16 + 2 * ty + 1];
                float4 b0 = cur[ck * 32 + 2 * tx];
                float4 b1 = cur[ck * 32 + 2 * tx + 1];
                float av[8] = {a0.x, a0.y, a0.z, a0.w, a1.x, a1.y, a1.z, a1.w};
                float bv[8] = {b0.x, b0.y, b0.z, b0.w, b1.x, b1.y, b1.z, b1.w};
                #pragma unroll
                for (int qi = 0; qi < 8; ++qi)
                    #pragma unroll
                    for (int kj = 0; kj < 8; ++kj)
                        acc[qi][kj] = fmaf(av[qi], bv[kj], acc[qi][kj]);
            }
            if (cc < 7) {                          // store into other buffer
                float4* nxt = cs4 + ((cc + 1) & 1) * 1024;
                #pragma unroll
                for (int j = 0; j < 8; ++j) {
                    int f = tid + 128 * j;
                    nxt[(f >> 5) * 32 + (f & 31)] = pf[j];
                }
                __syncthreads();
            }
        }

        // ---- epilogue: distances + running argmin (k ascending) ----
        float4 bn0 = ((const float4*)bn)[kt * 32 + 2 * tx];
        float4 bn1 = ((const float4*)bn)[kt * 32 + 2 * tx + 1];
        float bnv[8] = {bn0.x, bn0.y, bn0.z, bn0.w, bn1.x, bn1.y, bn1.z, bn1.w};
        #pragma unroll
        for (int qi = 0; qi < 8; ++qi)
            #pragma unroll
            for (int kj = 0; kj < 8; ++kj) {
                float d = fmaf(-2.f, acc[qi][kj], __fadd_rn(Aqv[qi], bnv[kj]));
                if (d < mv[qi]) {                   // strict < keeps lowest k
                    mv[qi] = d;
                    mi[qi] = k0g + kt * 128 + 8 * tx + kj;
                }
            }
        __syncthreads();   // before next kt reuses cs buffer 0
    }

    // ---- reduce across the 16 tx lanes (in-warp), lowest-k tie-break ----
    #pragma unroll
    for (int qi = 0; qi < 8; ++qi) {
        #pragma unroll
        for (int off = 1; off <= 8; off <<= 1) {
            float om = __shfl_xor_sync(0xffffffffu, mv[qi], off);
            int   oi = __shfl_xor_sync(0xffffffffu, mi[qi], off);
            if (om < mv[qi] || (om == mv[qi] && oi < mi[qi])) {
                mv[qi] = om; mi[qi] = oi;
            }
        }
        if (tx == 0) {
            int q = n0 + 8 * ty + qi;
            g_d2[half * Nq + q] = mv[qi];
            g_k2[half * Nq + q] = mi[qi];
        }
    }
}

// ---------------------------------------------------------------------------
// Merge the two code-half candidates (tie keeps half 0 = lower k, matching
// jnp.argmin first occurrence) AND produce per-block loss partial sums
// (deterministic: fixed range per block, fixed shared-memory tree).
// ---------------------------------------------------------------------------
__global__ void merge_kernel() {
    __shared__ double sd[256];
    int q = blockIdx.x * blockDim.x + threadIdx.x;
    float d0 = g_d2[q], d1 = g_d2[Nq + q];
    int   k0 = g_k2[q], k1 = g_k2[Nq + q];
    if (d1 < d0) { d0 = d1; k0 = k1; }
    g_idx[q] = k0;
    sd[threadIdx.x] = (double)d0;
    __syncthreads();
    for (int r = 128; r > 0; r >>= 1) {
        if (threadIdx.x < r) sd[threadIdx.x] += sd[threadIdx.x + r];
        __syncthreads();
    }
    if (threadIdx.x == 0) g_lpart[blockIdx.x] = sd[0];
}

// ---------------------------------------------------------------------------
// Fused epilogue: blocks 0..4095 write zq_st (vectorized, exact reference
// rounding); blocks 4096..4351 write idx-as-float; block 4352 reduces the
// 256 loss partials (tiny — no straggler).
// ---------------------------------------------------------------------------
__global__ void __launch_bounds__(256) epilogue_kernel(
        float* __restrict__ out, const float* __restrict__ z,
        int has_idx, int loss_off) {
    int p = blockIdx.x;
    if (p < 4096) {
        int b = p >> 8, c = p & 255;
        const float* row = g_cbT + (size_t)c * Kc;        // 4KB, L1-hot
        const int4*  id4 = (const int4*)(g_idx + b * HWc);
        const float4* zp4 = (const float4*)(z + (size_t)p * HWc);
        float4* o4 = (float4*)(out + (size_t)p * HWc);
        #pragma unroll
        for (int i = 0; i < 4; ++i) {
            int v = threadIdx.x + 256 * i;
            float4 zc = zp4[v];
            int4 id = id4[v];
            float4 r;
            r.x = __fadd_rn(zc.x, __fsub_rn(row[id.x], zc.x));
            r.y = __fadd_rn(zc.y, __fsub_rn(row[id.y], zc.y));
            r.z = __fadd_rn(zc.z, __fsub_rn(row[id.z], zc.z));
            r.w = __fadd_rn(zc.w, __fsub_rn(row[id.w], zc.w));
            o4[v] = r;
        }
    } else if (p < 4352) {
        if (has_idx) {
            int n = (p - 4096) * 256 + threadIdx.x;
            out[ZQ_ELEMS + n] = (float)g_idx[n];
        }
    } else {
        if (loss_off >= 0) {
            __shared__ double sd[256];
            sd[threadIdx.x] = g_lpart[threadIdx.x];
            __syncthreads();
            for (int r = 128; r > 0; r >>= 1) {
                if (threadIdx.x < r) sd[threadIdx.x] += sd[threadIdx.x + r];
                __syncthreads();
            }
            if (threadIdx.x == 0)
                out[loss_off] = (float)(0.75 * sd[0] / (double)ZQ_ELEMS);
        }
    }
}

// ---------------------------------------------------------------------------
extern "C" void kernel_launch(void* const* d_in, const int* in_sizes, int n_in,
                              void* d_out, int out_size) {
    const float* z  = (const float*)d_in[0];   // [B,C,H,W] fp32
    const float* cb = (const float*)d_in[1];   // [K,C]     fp32
    float* out = (float*)d_out;

    cudaFuncSetAttribute(vq_main, cudaFuncAttributeMaxDynamicSharedMemorySize, SMEM_BYTES);

    int has_idx = (out_size >= ZQ_ELEMS + Nq) ? 1 : 0;
    int loss_off = -1;
    if (out_size >= ZQ_ELEMS + Nq + 1) loss_off = ZQ_ELEMS + Nq;
    else if (out_size == ZQ_ELEMS + 1) loss_off = ZQ_ELEMS;

    prep_kernel<<<Kc, 256>>>(cb);
    vq_main<<<2 * (Nq / 64), 128, SMEM_BYTES>>>(z);
    merge_kernel<<<Nq / 256, 256>>>();
    epilogue_kernel<<<4353, 256>>>(out, z, has_idx, loss_off);
}